// round 10
// baseline (speedup 1.0000x reference)
#include <cuda_runtime.h>
#include <cuda_bf16.h>
#include <math.h>

#define Bsz   32
#define Mrows 65536
#define Wc    64
#define Kk    8
#define Rr    9
#define INF_  512
#define IFACE 138
#define NBLK  64                       // distance blocks per batch
#define ROWS_PER_BLK (Mrows / NBLK)    // 1024
#define ULLMAX 0xFFFFFFFFFFFFFFFFull

// Output layout: gathered[:, :8, :] (32*8*64) | read_weights_new (32*1*9) | gathered (32*9*64)
#define OUT0_OFF 0
#define OUT1_OFF 16384
#define OUT2_OFF 16672

typedef unsigned long long u64;

// ---------------- device scratch (no allocation allowed) ----------------
__device__ __align__(16) float g_q[Bsz * Wc];          // read_query per batch
__device__ __align__(16) float g_rv[Bsz * Rr * Wc];    // updated read vectors
__device__ float              g_drv[Bsz * Rr];         // ||rv - q||^2
__device__ int                g_flag[Mrows];           // scattered pos -> k (valid only where mask bit set)
__device__ unsigned           g_mask[Mrows / 32];      // per-(block,leader) bitmask (8 KB)
__device__ u64                g_cand[Bsz * NBLK * Kk]; // phase-A candidates
__device__ unsigned           g_cnt[Bsz];              // per-batch done counters (reset each replay)

// Mask addressing: for row m,  word = (m>>10)*32 + (m&31),  bit = (m>>5)&31.
// A leader (block blk, slot L = m&31) owns exactly one word = its 32 rows.

// ---------------- packed f32x2 helpers (PTX-only; ptxas won't auto-fuse) ----------------
__device__ __forceinline__ u64 pack2(float lo, float hi) {
    u64 r; asm("mov.b64 %0,{%1,%2};" : "=l"(r) : "f"(lo), "f"(hi)); return r;
}
__device__ __forceinline__ void unpack2(u64 v, float& lo, float& hi) {
    asm("mov.b64 {%0,%1},%2;" : "=f"(lo), "=f"(hi) : "l"(v));
}
__device__ __forceinline__ u64 addx2(u64 a, u64 b) {
    u64 r; asm("add.rn.f32x2 %0,%1,%2;" : "=l"(r) : "l"(a), "l"(b)); return r;
}
__device__ __forceinline__ u64 mulx2(u64 a, u64 b) {
    u64 r; asm("mul.rn.f32x2 %0,%1,%2;" : "=l"(r) : "l"(a), "l"(b)); return r;
}
__device__ __forceinline__ u64 fmax2(u64 a, u64 b, u64 c) {
    u64 r; asm("fma.rn.f32x2 %0,%1,%2,%3;" : "=l"(r) : "l"(a), "l"(b), "l"(c)); return r;
}

// ---------------- K1: fused setup ----------------
// blocks 0..31 : iface/ww/rv/d_rv for batch b
// block 32     : zero mask + counters, build scatter table (last j wins, k = j%9)
__global__ __launch_bounds__(256) void k_setup(
    const float* __restrict__ xi, const float* __restrict__ W,
    const float* __restrict__ bias, const float* __restrict__ read_weights,
    const float* __restrict__ read_vectors, const int* __restrict__ read_positions)
{
    int b = blockIdx.x, t = threadIdx.x;

    if (b == Bsz) {
        __shared__ int s_pos[Bsz * Rr];
        #pragma unroll
        for (int i = 0; i < 8; i++) g_mask[t + i * 256] = 0u;
        if (t < Bsz) g_cnt[t] = 0u;
        for (int i = t; i < Bsz * Rr; i += 256) s_pos[i] = read_positions[i];
        __syncthreads();
        for (int j = t; j < Bsz * Rr; j += 256) {
            int p = s_pos[j];
            bool win = true;
            for (int j2 = j + 1; j2 < Bsz * Rr; j2++)
                if (s_pos[j2] == p) { win = false; break; }
            if (win) {
                g_flag[p] = j % Rr;
                atomicOr(&g_mask[(p >> 10) * 32 + (p & 31)], 1u << ((p >> 5) & 31));
            }
        }
        return;
    }

    __shared__ float s_xi[INF_];
    __shared__ float s_if[IFACE];
    __shared__ float s_ww[Rr];
    __shared__ float s_rv[Rr * Wc];

    for (int i = t; i < INF_; i += 256) s_xi[i] = xi[b * INF_ + i];
    __syncthreads();

    if (t < IFACE) {
        float a0 = 0.f, a1 = 0.f, a2 = 0.f, a3 = 0.f;
        #pragma unroll 2
        for (int i = 0; i < INF_; i += 8) {
            a0 = fmaf(s_xi[i + 0], W[(i + 0) * IFACE + t], a0);
            a1 = fmaf(s_xi[i + 1], W[(i + 1) * IFACE + t], a1);
            a2 = fmaf(s_xi[i + 2], W[(i + 2) * IFACE + t], a2);
            a3 = fmaf(s_xi[i + 3], W[(i + 3) * IFACE + t], a3);
            a0 = fmaf(s_xi[i + 4], W[(i + 4) * IFACE + t], a0);
            a1 = fmaf(s_xi[i + 5], W[(i + 5) * IFACE + t], a1);
            a2 = fmaf(s_xi[i + 6], W[(i + 6) * IFACE + t], a2);
            a3 = fmaf(s_xi[i + 7], W[(i + 7) * IFACE + t], a3);
        }
        s_if[t] = (a0 + a1) + (a2 + a3) + bias[t];
    }
    __syncthreads();

    if (t < Wc) g_q[b * Wc + t] = s_if[t];
    if (t < Rr) {
        float gate = 1.0f / (1.0f + expf(-s_if[IFACE - 1]));
        float ig   = s_if[2 * Wc + t];
        float rw   = read_weights[b * Rr + t];
        s_ww[t] = gate * (ig * rw + (1.0f - ig));
    }
    __syncthreads();

    for (int i = t; i < Rr * Wc; i += 256) {
        int r = i >> 6, w = i & 63;
        float v = read_vectors[b * Rr * Wc + i] + s_ww[r] * s_if[Wc + w];
        s_rv[i] = v;
        g_rv[b * Rr * Wc + i] = v;
    }
    __syncthreads();

    if (t < Rr) {
        float acc = 0.0f;
        for (int w = 0; w < Wc; w++) {
            float d = s_rv[t * Wc + w] - s_if[w];
            acc = fmaf(d, d, acc);
        }
        g_drv[b * Rr + t] = acc;
    }
}

// ---------------- distance for one row (8 lanes x 32B), packed f32x2 ----------------
__device__ __forceinline__ float row_dist(longlong2 r0, longlong2 r1,
                                          u64 nq0, u64 nq1, u64 nq2, u64 nq3) {
    u64 d0 = addx2((u64)r0.x, nq0);
    u64 d1 = addx2((u64)r0.y, nq1);
    u64 d2 = addx2((u64)r1.x, nq2);
    u64 d3 = addx2((u64)r1.y, nq3);
    u64 acc = mulx2(d0, d0);
    acc = fmax2(d1, d1, acc);
    acc = fmax2(d2, d2, acc);
    acc = fmax2(d3, d3, acc);
    float lo, hi; unpack2(acc, lo, hi);
    float s = lo + hi;
    s += __shfl_xor_sync(0xffffffffu, s, 4, 8);
    s += __shfl_xor_sync(0xffffffffu, s, 2, 8);
    s += __shfl_xor_sync(0xffffffffu, s, 1, 8);
    return s;
}

// insert cand into sorted-asc smem array of 8 (caller guarantees cand < arr[7]);
// returns new threshold arr[7]. Rare path (~19x per leader per block).
__device__ __forceinline__ u64 smem_insert(u64* arr, u64 cand) {
    arr[7] = cand;
    #pragma unroll
    for (int j = 7; j >= 1; j--) {
        u64 a = arr[j], bv = arr[j - 1];
        if (a < bv) { arr[j - 1] = a; arr[j] = bv; }
    }
    return arr[7];
}

__device__ __forceinline__ void insert_cand(u64* best, u64 cand) {
    if (cand < best[7]) {
        best[7] = cand;
        #pragma unroll
        for (int i = 7; i >= 1; i--) {
            if (best[i] < best[i - 1]) {
                u64 tmp = best[i - 1]; best[i - 1] = best[i]; best[i] = tmp;
            }
        }
    }
}

// ---------------- K2: streaming distance + per-block top-8 + fused finalize ----------------
__global__ __launch_bounds__(256, 6) void k_dist(
    const float* __restrict__ sparse, const int* __restrict__ last_used,
    float* __restrict__ out)
{
    __shared__ u64 s_best[32][Kk];             // per-leader top-8 (sorted asc)

    const int b    = blockIdx.y;
    const int t    = threadIdx.x;
    const int lane = t & 31, warp = t >> 5;
    const int lir  = lane & 7;                 // lane-in-row (8 lanes x 32B = 256B row)
    const int L    = warp * 4 + (lane >> 3);   // leader slot 0..31
    const int row0 = blockIdx.x * ROWS_PER_BLK;

    s_best[t >> 3][t & 7] = ULLMAX;            // init all 256 entries
    __syncthreads();

    // per-pass: 32 rows (block covers 8 warps x 4 rows); 32 passes of stride 32
    const longlong2* __restrict__ p =
        (const longlong2*)(sparse + ((size_t)b * Mrows + row0 + L) * Wc) + lir * 2;

    const float4* qp = (const float4*)(g_q + b * Wc + lir * 8);
    float4 qa = qp[0], qb = qp[1];
    u64 nq0 = pack2(-qa.x, -qa.y), nq1 = pack2(-qa.z, -qa.w);
    u64 nq2 = pack2(-qb.x, -qb.y), nq3 = pack2(-qb.z, -qb.w);

    unsigned mk = 0;
    if (lir == 0) mk = g_mask[blockIdx.x * 32 + L];

    u64 thresh = ULLMAX;
    const int mbase = row0 + L;

    #pragma unroll 1
    for (int pass = 0; pass < 32; pass += 2, p += 1024) {   // 2 passes * 32 rows * 256B
        longlong2 a0 = __ldcs(p);
        longlong2 a1 = __ldcs(p + 1);
        longlong2 c0 = __ldcs(p + 512);
        longlong2 c1 = __ldcs(p + 513);

        float s0 = row_dist(a0, a1, nq0, nq1, nq2, nq3);
        float s1 = row_dist(c0, c1, nq0, nq1, nq2, nq3);

        if (lir == 0) {
            int m0 = mbase + (pass << 5);
            int m1 = m0 + 32;
            if (mk != 0u) {
                if ((mk >> pass) & 1u)       s0 = g_drv[b * Rr + g_flag[m0]];
                if ((mk >> (pass + 1)) & 1u) s1 = g_drv[b * Rr + g_flag[m1]];
            }
            u64 cand0 = ((u64)__float_as_uint(s0) << 32) | (unsigned)m0;
            u64 cand1 = ((u64)__float_as_uint(s1) << 32) | (unsigned)m1;
            if (cand0 < thresh) thresh = smem_insert(&s_best[L][0], cand0);
            if (cand1 < thresh) thresh = smem_insert(&s_best[L][0], cand1);
        }
    }
    __syncthreads();

    // block merge: 32 leaders x 8 sorted (in smem) -> warp0 extracts global top-8
    if (warp == 0) {
        u64 v[Kk];
        #pragma unroll
        for (int i = 0; i < Kk; i++) v[i] = s_best[lane][i];   // sorted asc per lane

        u64* outc = g_cand + ((size_t)b * NBLK + blockIdx.x) * Kk;
        #pragma unroll 1
        for (int r = 0; r < Kk; r++) {
            u64 my = v[0];
            u64 g = my;
            #pragma unroll
            for (int off = 16; off; off >>= 1) {
                u64 o = __shfl_xor_sync(0xffffffffu, g, off);
                if (o < g) g = o;
            }
            if (g == my) {
                #pragma unroll
                for (int i = 0; i < Kk - 1; i++) v[i] = v[i + 1];
                v[Kk - 1] = ULLMAX;
            }
            if (lane == 0) outc[r] = g;
        }
    }

    // ---- last-block-per-batch fused finalize (threadfence-reduction pattern) ----
    __shared__ int s_last;
    if (t == 0) {
        __threadfence();                       // publish this block's g_cand
        unsigned old = atomicAdd(&g_cnt[b], 1u);
        s_last = (old == NBLK - 1);
        __threadfence();                       // acquire other blocks' g_cand
    }
    __syncthreads();
    if (!s_last) return;

    __shared__ u64   s_sel[Kk];
    __shared__ int   s_pos[Rr];
    __shared__ float s_nd[Rr];

    if (t < 32) {
        const u64* cb = g_cand + (size_t)b * NBLK * Kk;
        u64 fb[Kk];
        #pragma unroll
        for (int i = 0; i < Kk; i++) fb[i] = ULLMAX;
        #pragma unroll
        for (int i = 0; i < 16; i++) insert_cand(fb, cb[lane * 16 + i]);
        #pragma unroll 1
        for (int r = 0; r < Kk; r++) {
            u64 my = fb[0];
            u64 g = my;
            #pragma unroll
            for (int off = 16; off; off >>= 1) {
                u64 o = __shfl_xor_sync(0xffffffffu, g, off);
                if (o < g) g = o;
            }
            if (g == my) {
                #pragma unroll
                for (int j = 0; j < Kk - 1; j++) fb[j] = fb[j + 1];
                fb[Kk - 1] = ULLMAX;
            }
            if (lane == 0) s_sel[r] = g;
        }
    }
    __syncthreads();

    if (t < Rr) {
        float d_t = (t < Kk) ? __uint_as_float((unsigned)(s_sel[t] >> 32)) : 0.0f;
        int   p_t = (t < Kk) ? (int)(unsigned)(s_sel[t] & 0xFFFFFFFFu) : last_used[b];
        float maxd = 0.0f;
        #pragma unroll
        for (int i = 0; i < Kk; i++) {
            float di = __uint_as_float((unsigned)(s_sel[i] >> 32));
            if (di > maxd) maxd = di;
        }
        s_pos[t] = p_t;
        s_nd[t]  = d_t / maxd;
        out[OUT1_OFF + b * Rr + t] = s_nd[t];
    }
    __syncthreads();

    // gather 9 rows (mask-aware: scattered rows come from rv)
    for (int i = t; i < Rr * Wc; i += 256) {
        int k = i >> 6, w = i & 63;
        int m = s_pos[k];
        unsigned mw = g_mask[(m >> 10) * 32 + (m & 31)];
        int f = ((mw >> ((m >> 5) & 31)) & 1u) ? g_flag[m] : -1;
        float val = (f >= 0) ? g_rv[b * Rr * Wc + f * Wc + w]
                             : sparse[((size_t)b * Mrows + m) * Wc + w];
        out[OUT2_OFF + b * Rr * Wc + i] = val;
        if (k < Kk) out[OUT0_OFF + b * Kk * Wc + k * Wc + w] = val;
    }
}

// ---------------- launch ----------------
extern "C" void kernel_launch(void* const* d_in, const int* in_sizes, int n_in,
                              void* d_out, int out_size) {
    const float* xi            = (const float*)d_in[0];
    const float* sparse        = (const float*)d_in[1];
    const float* read_weights  = (const float*)d_in[2];
    const float* read_vectors  = (const float*)d_in[3];
    const float* W             = (const float*)d_in[4];
    const float* bias          = (const float*)d_in[5];
    const int*   read_positions= (const int*)d_in[6];
    const int*   last_used     = (const int*)d_in[7];
    float* out = (float*)d_out;

    k_setup<<<Bsz + 1, 256>>>(xi, W, bias, read_weights, read_vectors, read_positions);
    k_dist<<<dim3(NBLK, Bsz), 256>>>(sparse, last_used, out);
}

// round 11
// speedup vs baseline: 1.2204x; 1.2204x over previous
#include <cuda_runtime.h>
#include <cuda_bf16.h>
#include <math.h>

#define Bsz   32
#define Mrows 65536
#define Wc    64
#define Kk    8
#define Rr    9
#define INF_  512
#define IFACE 138
#define NBLK  64                       // distance blocks per batch
#define ROWS_PER_BLK (Mrows / NBLK)    // 1024
#define ULLMAX 0xFFFFFFFFFFFFFFFFull

// Output layout: gathered[:, :8, :] (32*8*64) | read_weights_new (32*1*9) | gathered (32*9*64)
#define OUT0_OFF 0
#define OUT1_OFF 16384
#define OUT2_OFF 16672

typedef unsigned long long u64;

// ---------------- device scratch (no allocation allowed) ----------------
__device__ __align__(16) float g_q[Bsz * Wc];          // read_query per batch
__device__ __align__(16) float g_rv[Bsz * Rr * Wc];    // updated read vectors
__device__ float              g_drv[Bsz * Rr];         // ||rv - q||^2
__device__ int                g_flag[Mrows];           // scattered pos -> k (valid only where mask bit set)
__device__ unsigned           g_mask[Mrows / 32];      // per-(block,leader) bitmask (8 KB)
__device__ u64                g_cand[Bsz * NBLK * Kk]; // phase-A candidates
__device__ unsigned           g_cnt[Bsz];              // per-batch done counters (reset each replay)

// Mask addressing: for row m,  word = (m>>10)*32 + (m&31),  bit = (m>>5)&31.

// ---------------- packed f32x2 helpers (PTX-only; ptxas won't auto-fuse) ----------------
__device__ __forceinline__ u64 pack2(float lo, float hi) {
    u64 r; asm("mov.b64 %0,{%1,%2};" : "=l"(r) : "f"(lo), "f"(hi)); return r;
}
__device__ __forceinline__ void unpack2(u64 v, float& lo, float& hi) {
    asm("mov.b64 {%0,%1},%2;" : "=f"(lo), "=f"(hi) : "l"(v));
}
__device__ __forceinline__ u64 addx2(u64 a, u64 b) {
    u64 r; asm("add.rn.f32x2 %0,%1,%2;" : "=l"(r) : "l"(a), "l"(b)); return r;
}
__device__ __forceinline__ u64 mulx2(u64 a, u64 b) {
    u64 r; asm("mul.rn.f32x2 %0,%1,%2;" : "=l"(r) : "l"(a), "l"(b)); return r;
}
__device__ __forceinline__ u64 fmax2(u64 a, u64 b, u64 c) {
    u64 r; asm("fma.rn.f32x2 %0,%1,%2,%3;" : "=l"(r) : "l"(a), "l"(b), "l"(c)); return r;
}

// ---------------- K1: fused setup ----------------
// blocks 0..31 : iface/ww/rv/d_rv for batch b
// block 32     : zero mask + counters, build scatter table (last j wins, k = j%9)
__global__ __launch_bounds__(256) void k_setup(
    const float* __restrict__ xi, const float* __restrict__ W,
    const float* __restrict__ bias, const float* __restrict__ read_weights,
    const float* __restrict__ read_vectors, const int* __restrict__ read_positions)
{
    int b = blockIdx.x, t = threadIdx.x;

    if (b == Bsz) {
        __shared__ int s_pos[Bsz * Rr];
        #pragma unroll
        for (int i = 0; i < 8; i++) g_mask[t + i * 256] = 0u;
        if (t < Bsz) g_cnt[t] = 0u;
        for (int i = t; i < Bsz * Rr; i += 256) s_pos[i] = read_positions[i];
        __syncthreads();
        for (int j = t; j < Bsz * Rr; j += 256) {
            int p = s_pos[j];
            bool win = true;
            for (int j2 = j + 1; j2 < Bsz * Rr; j2++)
                if (s_pos[j2] == p) { win = false; break; }
            if (win) {
                g_flag[p] = j % Rr;
                atomicOr(&g_mask[(p >> 10) * 32 + (p & 31)], 1u << ((p >> 5) & 31));
            }
        }
        return;
    }

    __shared__ float s_xi[INF_];
    __shared__ float s_if[IFACE];
    __shared__ float s_ww[Rr];
    __shared__ float s_rv[Rr * Wc];

    for (int i = t; i < INF_; i += 256) s_xi[i] = xi[b * INF_ + i];
    __syncthreads();

    if (t < IFACE) {
        float a0 = 0.f, a1 = 0.f, a2 = 0.f, a3 = 0.f;
        #pragma unroll 2
        for (int i = 0; i < INF_; i += 8) {
            a0 = fmaf(s_xi[i + 0], W[(i + 0) * IFACE + t], a0);
            a1 = fmaf(s_xi[i + 1], W[(i + 1) * IFACE + t], a1);
            a2 = fmaf(s_xi[i + 2], W[(i + 2) * IFACE + t], a2);
            a3 = fmaf(s_xi[i + 3], W[(i + 3) * IFACE + t], a3);
            a0 = fmaf(s_xi[i + 4], W[(i + 4) * IFACE + t], a0);
            a1 = fmaf(s_xi[i + 5], W[(i + 5) * IFACE + t], a1);
            a2 = fmaf(s_xi[i + 6], W[(i + 6) * IFACE + t], a2);
            a3 = fmaf(s_xi[i + 7], W[(i + 7) * IFACE + t], a3);
        }
        s_if[t] = (a0 + a1) + (a2 + a3) + bias[t];
    }
    __syncthreads();

    if (t < Wc) g_q[b * Wc + t] = s_if[t];
    if (t < Rr) {
        float gate = 1.0f / (1.0f + expf(-s_if[IFACE - 1]));
        float ig   = s_if[2 * Wc + t];
        float rw   = read_weights[b * Rr + t];
        s_ww[t] = gate * (ig * rw + (1.0f - ig));
    }
    __syncthreads();

    for (int i = t; i < Rr * Wc; i += 256) {
        int r = i >> 6, w = i & 63;
        float v = read_vectors[b * Rr * Wc + i] + s_ww[r] * s_if[Wc + w];
        s_rv[i] = v;
        g_rv[b * Rr * Wc + i] = v;
    }
    __syncthreads();

    if (t < Rr) {
        float acc = 0.0f;
        for (int w = 0; w < Wc; w++) {
            float d = s_rv[t * Wc + w] - s_if[w];
            acc = fmaf(d, d, acc);
        }
        g_drv[b * Rr + t] = acc;
    }
}

// ---------------- distance for one row (8 lanes x 32B), packed f32x2 ----------------
// result is left in ALL 8 lanes of the group (xor-reduction)
__device__ __forceinline__ float row_dist(longlong2 r0, longlong2 r1,
                                          u64 nq0, u64 nq1, u64 nq2, u64 nq3) {
    u64 d0 = addx2((u64)r0.x, nq0);
    u64 d1 = addx2((u64)r0.y, nq1);
    u64 d2 = addx2((u64)r1.x, nq2);
    u64 d3 = addx2((u64)r1.y, nq3);
    u64 acc = mulx2(d0, d0);
    acc = fmax2(d1, d1, acc);
    acc = fmax2(d2, d2, acc);
    acc = fmax2(d3, d3, acc);
    float lo, hi; unpack2(acc, lo, hi);
    float s = lo + hi;
    s += __shfl_xor_sync(0xffffffffu, s, 4, 8);
    s += __shfl_xor_sync(0xffffffffu, s, 2, 8);
    s += __shfl_xor_sync(0xffffffffu, s, 1, 8);
    return s;
}

__device__ __forceinline__ void insert_cand(u64* best, u64 cand) {
    if (cand < best[7]) {
        best[7] = cand;
        #pragma unroll
        for (int i = 7; i >= 1; i--) {
            if (best[i] < best[i - 1]) {
                u64 tmp = best[i - 1]; best[i - 1] = best[i]; best[i] = tmp;
            }
        }
    }
}

// ---------------- K2: streaming distance + per-block top-8 + fused finalize ----------------
// Top-8 is DISTRIBUTED across the 8 lanes of each row-group: lane lir holds the
// rank-lir candidate (sorted asc). One u64 of state per thread instead of 8.
__global__ __launch_bounds__(256) void k_dist(
    const float* __restrict__ sparse, const int* __restrict__ last_used,
    float* __restrict__ out)
{
    const int b    = blockIdx.y;
    const int t    = threadIdx.x;
    const int lane = t & 31, warp = t >> 5;
    const int lir  = lane & 7;                 // lane-in-row (8 lanes x 32B = 256B row)
    const int L    = warp * 4 + (lane >> 3);   // group slot 0..31
    const int row0 = blockIdx.x * ROWS_PER_BLK;
    const unsigned gmask = 0xFFu << (lane & 24);   // member mask of this 8-lane group

    // per-pass: 32 rows (block covers 8 warps x 4 rows); 32 passes of stride 32
    const longlong2* __restrict__ p =
        (const longlong2*)(sparse + ((size_t)b * Mrows + row0 + L) * Wc) + lir * 2;

    const float4* qp = (const float4*)(g_q + b * Wc + lir * 8);
    float4 qa = qp[0], qb = qp[1];
    u64 nq0 = pack2(-qa.x, -qa.y), nq1 = pack2(-qa.z, -qa.w);
    u64 nq2 = pack2(-qb.x, -qb.y), nq3 = pack2(-qb.z, -qb.w);

    const unsigned mk = g_mask[blockIdx.x * 32 + L];   // same word in all 8 lanes of group

    u64 v = ULLMAX;            // my rank-lir candidate (sorted asc across group)
    u64 thresh = ULLMAX;       // current rank-7 value (uniform in group)
    const int mbase = row0 + L;

    #pragma unroll 1
    for (int pass = 0; pass < 32; pass += 2, p += 1024) {   // 2 rows per group per iter
        longlong2 a0 = __ldcs(p);
        longlong2 a1 = __ldcs(p + 1);
        longlong2 c0 = __ldcs(p + 512);
        longlong2 c1 = __ldcs(p + 513);

        float s0 = row_dist(a0, a1, nq0, nq1, nq2, nq3);
        float s1 = row_dist(c0, c1, nq0, nq1, nq2, nq3);

        int m0 = mbase + (pass << 5);
        int m1 = m0 + 32;
        if (mk != 0u) {        // group-uniform rare path
            if ((mk >> pass) & 1u)       s0 = g_drv[b * Rr + g_flag[m0]];
            if ((mk >> (pass + 1)) & 1u) s1 = g_drv[b * Rr + g_flag[m1]];
        }
        u64 cand0 = ((u64)__float_as_uint(s0) << 32) | (unsigned)m0;
        u64 cand1 = ((u64)__float_as_uint(s1) << 32) | (unsigned)m1;

        // distributed insert (group-uniform branch; rare)
        if (cand0 < thresh) {
            u64 vprev = __shfl_up_sync(gmask, v, 1, 8);
            bool pprev = (lir != 0) && (cand0 < vprev);
            if (cand0 < v) v = pprev ? vprev : cand0;
            thresh = __shfl_sync(gmask, v, 7, 8);
        }
        if (cand1 < thresh) {
            u64 vprev = __shfl_up_sync(gmask, v, 1, 8);
            bool pprev = (lir != 0) && (cand1 < vprev);
            if (cand1 < v) v = pprev ? vprev : cand1;
            thresh = __shfl_sync(gmask, v, 7, 8);
        }
    }

    // block merge: each lane writes its rank-lir value; 32 groups x 8 sorted asc
    __shared__ u64 s_c[32 * Kk];
    s_c[L * Kk + lir] = v;
    __syncthreads();

    if (warp == 0) {
        u64 vv[Kk];
        #pragma unroll
        for (int i = 0; i < Kk; i++) vv[i] = s_c[lane * Kk + i];   // sorted asc per lane

        u64* outc = g_cand + ((size_t)b * NBLK + blockIdx.x) * Kk;
        #pragma unroll 1
        for (int r = 0; r < Kk; r++) {
            u64 my = vv[0];
            u64 g = my;
            #pragma unroll
            for (int off = 16; off; off >>= 1) {
                u64 o = __shfl_xor_sync(0xffffffffu, g, off);
                if (o < g) g = o;
            }
            if (g == my) {
                #pragma unroll
                for (int i = 0; i < Kk - 1; i++) vv[i] = vv[i + 1];
                vv[Kk - 1] = ULLMAX;
            }
            if (lane == 0) outc[r] = g;
        }
    }

    // ---- last-block-per-batch fused finalize (threadfence-reduction pattern) ----
    __shared__ int s_last;
    if (t == 0) {
        __threadfence();                       // publish this block's g_cand
        unsigned old = atomicAdd(&g_cnt[b], 1u);
        s_last = (old == NBLK - 1);
        __threadfence();                       // acquire other blocks' g_cand
    }
    __syncthreads();
    if (!s_last) return;

    __shared__ u64   s_sel[Kk];
    __shared__ int   s_pos[Rr];
    __shared__ float s_nd[Rr];

    if (t < 32) {
        const u64* cb = g_cand + (size_t)b * NBLK * Kk;
        u64 fb[Kk];
        #pragma unroll
        for (int i = 0; i < Kk; i++) fb[i] = ULLMAX;
        #pragma unroll
        for (int i = 0; i < 16; i++) insert_cand(fb, cb[lane * 16 + i]);
        #pragma unroll 1
        for (int r = 0; r < Kk; r++) {
            u64 my = fb[0];
            u64 g = my;
            #pragma unroll
            for (int off = 16; off; off >>= 1) {
                u64 o = __shfl_xor_sync(0xffffffffu, g, off);
                if (o < g) g = o;
            }
            if (g == my) {
                #pragma unroll
                for (int j = 0; j < Kk - 1; j++) fb[j] = fb[j + 1];
                fb[Kk - 1] = ULLMAX;
            }
            if (lane == 0) s_sel[r] = g;
        }
    }
    __syncthreads();

    if (t < Rr) {
        float d_t = (t < Kk) ? __uint_as_float((unsigned)(s_sel[t] >> 32)) : 0.0f;
        int   p_t = (t < Kk) ? (int)(unsigned)(s_sel[t] & 0xFFFFFFFFu) : last_used[b];
        float maxd = 0.0f;
        #pragma unroll
        for (int i = 0; i < Kk; i++) {
            float di = __uint_as_float((unsigned)(s_sel[i] >> 32));
            if (di > maxd) maxd = di;
        }
        s_pos[t] = p_t;
        s_nd[t]  = d_t / maxd;
        out[OUT1_OFF + b * Rr + t] = s_nd[t];
    }
    __syncthreads();

    // gather 9 rows (mask-aware: scattered rows come from rv)
    for (int i = t; i < Rr * Wc; i += 256) {
        int k = i >> 6, w = i & 63;
        int m = s_pos[k];
        unsigned mw = g_mask[(m >> 10) * 32 + (m & 31)];
        int f = ((mw >> ((m >> 5) & 31)) & 1u) ? g_flag[m] : -1;
        float val = (f >= 0) ? g_rv[b * Rr * Wc + f * Wc + w]
                             : sparse[((size_t)b * Mrows + m) * Wc + w];
        out[OUT2_OFF + b * Rr * Wc + i] = val;
        if (k < Kk) out[OUT0_OFF + b * Kk * Wc + k * Wc + w] = val;
    }
}

// ---------------- launch ----------------
extern "C" void kernel_launch(void* const* d_in, const int* in_sizes, int n_in,
                              void* d_out, int out_size) {
    const float* xi            = (const float*)d_in[0];
    const float* sparse        = (const float*)d_in[1];
    const float* read_weights  = (const float*)d_in[2];
    const float* read_vectors  = (const float*)d_in[3];
    const float* W             = (const float*)d_in[4];
    const float* bias          = (const float*)d_in[5];
    const int*   read_positions= (const int*)d_in[6];
    const int*   last_used     = (const int*)d_in[7];
    float* out = (float*)d_out;

    k_setup<<<Bsz + 1, 256>>>(xi, W, bias, read_weights, read_vectors, read_positions);
    k_dist<<<dim3(NBLK, Bsz), 256>>>(sparse, last_used, out);
}